// round 1
// baseline (speedup 1.0000x reference)
#include <cuda_runtime.h>
#include <math.h>

// Problem constants
#define T_TOKENS 25088      // 8 * 3136
#define DMODEL   768
#define NHEAD    12
#define DHEAD    64
#define FFDIM    3072
#define WS2      49
#define NWIN     512        // T_TOKENS / 49
#define D3       2304       // 3 * DMODEL

// ---------------- scratch (device globals; no allocation allowed) ----------------
__device__ __align__(128) float g_y[(size_t)T_TOKENS * DMODEL];     // LN output
__device__ __align__(128) float g_qkv[(size_t)T_TOKENS * D3];       // QKV
__device__ __align__(128) float g_o[(size_t)T_TOKENS * DMODEL];     // attention output
__device__ __align__(128) float g_h[(size_t)T_TOKENS * DMODEL];     // residual stream
__device__ __align__(128) float g_f[(size_t)T_TOKENS * FFDIM];      // FFN hidden

// ---------------- LayerNorm: one block per token, 256 threads ----------------
__global__ __launch_bounds__(256) void ln_kernel(
    const float* __restrict__ x, const float* __restrict__ w,
    const float* __restrict__ b, float* __restrict__ y)
{
    const int t = blockIdx.x;
    const float* xr = x + (size_t)t * DMODEL;
    float* yr = y + (size_t)t * DMODEL;
    const int tid = threadIdx.x;

    float v0 = xr[tid];
    float v1 = xr[tid + 256];
    float v2 = xr[tid + 512];
    float s = v0 + v1 + v2;
    float q = v0 * v0 + v1 * v1 + v2 * v2;

    #pragma unroll
    for (int off = 16; off > 0; off >>= 1) {
        s += __shfl_xor_sync(0xFFFFFFFFu, s, off);
        q += __shfl_xor_sync(0xFFFFFFFFu, q, off);
    }
    __shared__ float ss[8], sq[8];
    const int wid = tid >> 5, lid = tid & 31;
    if (lid == 0) { ss[wid] = s; sq[wid] = q; }
    __syncthreads();
    if (tid == 0) {
        float S = 0.f, Q = 0.f;
        #pragma unroll
        for (int i = 0; i < 8; i++) { S += ss[i]; Q += sq[i]; }
        float m = S * (1.0f / DMODEL);
        float var = Q * (1.0f / DMODEL) - m * m;
        ss[0] = m;
        sq[0] = rsqrtf(var + 1e-5f);
    }
    __syncthreads();
    const float m = ss[0], r = sq[0];
    yr[tid]       = (v0 - m) * r * w[tid]       + b[tid];
    yr[tid + 256] = (v1 - m) * r * w[tid + 256] + b[tid + 256];
    yr[tid + 512] = (v2 - m) * r * w[tid + 512] + b[tid + 512];
}

// ---------------- Windowed attention: one block per (window, head) ----------------
__global__ __launch_bounds__(256) void attn_kernel(
    const float* __restrict__ qkv, float* __restrict__ o)
{
    __shared__ float sq[WS2 * DHEAD];
    __shared__ float sk[WS2 * DHEAD];
    __shared__ float sv[WS2 * DHEAD];
    __shared__ float sscr[WS2 * WS2];

    const int w  = blockIdx.x / NHEAD;
    const int hd = blockIdx.x % NHEAD;
    const int t0 = w * WS2;
    const int tid = threadIdx.x;

    for (int i = tid; i < WS2 * DHEAD; i += 256) {
        int r = i / DHEAD, d = i % DHEAD;
        size_t base = (size_t)(t0 + r) * D3 + hd * DHEAD + d;
        sq[i] = qkv[base];
        sk[i] = qkv[base + DMODEL];
        sv[i] = qkv[base + 2 * DMODEL];
    }
    __syncthreads();

    for (int i = tid; i < WS2 * WS2; i += 256) {
        int qi = i / WS2, kj = i % WS2;
        float acc = 0.f;
        #pragma unroll
        for (int d = 0; d < DHEAD; d++)
            acc = fmaf(sq[qi * DHEAD + d], sk[kj * DHEAD + d], acc);
        sscr[i] = acc * 0.125f;   // 1/sqrt(64)
    }
    __syncthreads();

    if (tid < WS2) {
        float mx = -1e30f;
        #pragma unroll 7
        for (int j = 0; j < WS2; j++) mx = fmaxf(mx, sscr[tid * WS2 + j]);
        float sum = 0.f;
        #pragma unroll 7
        for (int j = 0; j < WS2; j++) {
            float e = __expf(sscr[tid * WS2 + j] - mx);
            sscr[tid * WS2 + j] = e;
            sum += e;
        }
        float inv = 1.0f / sum;
        #pragma unroll 7
        for (int j = 0; j < WS2; j++) sscr[tid * WS2 + j] *= inv;
    }
    __syncthreads();

    for (int i = tid; i < WS2 * DHEAD; i += 256) {
        int qi = i / DHEAD, d = i % DHEAD;
        float acc = 0.f;
        #pragma unroll
        for (int kj = 0; kj < WS2; kj++)
            acc = fmaf(sscr[qi * WS2 + kj], sv[kj * DHEAD + d], acc);
        o[(size_t)(t0 + qi) * DMODEL + hd * DHEAD + d] = acc;
    }
}

// ---------------- Tiled SGEMM:  C[M,N] = act(A[M,K] @ B[N,K]^T + bias) (+ res) ----
// BM=BN=128, BK=8, 256 threads, 8x8 accum per thread.
#define BM 128
#define BN 128
#define BK 8
#define TM 8
#define TN 8

template <bool GELU, bool RES>
__global__ __launch_bounds__(256) void sgemm_tn(
    const float* __restrict__ A,     // [M,K]
    const float* __restrict__ B,     // [N,K]
    const float* __restrict__ bias,  // [N]
    const float* __restrict__ res,   // [M,N] or null
    float* __restrict__ C,           // [M,N]
    int M, int N, int K)
{
    __shared__ float As[BK][BM];
    __shared__ float Bs[BK][BN];

    const int bm = blockIdx.y * BM;
    const int bn = blockIdx.x * BN;
    const int tid = threadIdx.x;
    const int tr = tid / 16;   // 0..15
    const int tc = tid % 16;   // 0..15

    const int lrow = tid >> 1;          // 0..127
    const int lcol = (tid & 1) * 4;     // 0 or 4
    const float* Aptr = A + (size_t)(bm + lrow) * K + lcol;
    const float* Bptr = B + (size_t)(bn + lrow) * K + lcol;

    float acc[TM][TN];
    #pragma unroll
    for (int i = 0; i < TM; i++)
        #pragma unroll
        for (int j = 0; j < TN; j++) acc[i][j] = 0.f;

    for (int k0 = 0; k0 < K; k0 += BK) {
        float4 a = *(const float4*)(Aptr + k0);
        float4 b = *(const float4*)(Bptr + k0);
        As[lcol + 0][lrow] = a.x; As[lcol + 1][lrow] = a.y;
        As[lcol + 2][lrow] = a.z; As[lcol + 3][lrow] = a.w;
        Bs[lcol + 0][lrow] = b.x; Bs[lcol + 1][lrow] = b.y;
        Bs[lcol + 2][lrow] = b.z; Bs[lcol + 3][lrow] = b.w;
        __syncthreads();

        #pragma unroll
        for (int k = 0; k < BK; k++) {
            float ra[TM], rb[TN];
            #pragma unroll
            for (int i = 0; i < TM; i++) ra[i] = As[k][tr * TM + i];
            #pragma unroll
            for (int j = 0; j < TN; j++) rb[j] = Bs[k][tc * TN + j];
            #pragma unroll
            for (int i = 0; i < TM; i++)
                #pragma unroll
                for (int j = 0; j < TN; j++)
                    acc[i][j] = fmaf(ra[i], rb[j], acc[i][j]);
        }
        __syncthreads();
    }

    #pragma unroll
    for (int i = 0; i < TM; i++) {
        const int m = bm + tr * TM + i;
        #pragma unroll
        for (int j = 0; j < TN; j++) {
            const int n = bn + tc * TN + j;
            float v = acc[i][j] + bias[n];
            if (GELU) v = 0.5f * v * (1.0f + erff(v * 0.70710678118654752f));
            if (RES)  v += res[(size_t)m * N + n];
            C[(size_t)m * N + n] = v;
        }
    }
}

// ---------------- host-side launch ----------------
extern "C" void kernel_launch(void* const* d_in, const int* in_sizes, int n_in,
                              void* d_out, int out_size)
{
    const float* x     = (const float*)d_in[0];
    const float* Wqkv  = (const float*)d_in[1];
    const float* bqkv  = (const float*)d_in[2];
    const float* Wo    = (const float*)d_in[3];
    const float* bo    = (const float*)d_in[4];
    const float* ln1_w = (const float*)d_in[5];
    const float* ln1_b = (const float*)d_in[6];
    const float* W1    = (const float*)d_in[7];
    const float* b1    = (const float*)d_in[8];
    const float* W2    = (const float*)d_in[9];
    const float* b2    = (const float*)d_in[10];
    const float* ln2_w = (const float*)d_in[11];
    const float* ln2_b = (const float*)d_in[12];
    float* out = (float*)d_out;

    static float *p_y = nullptr, *p_qkv = nullptr, *p_o = nullptr, *p_h = nullptr, *p_f = nullptr;
    if (!p_y) {
        cudaGetSymbolAddress((void**)&p_y,   g_y);
        cudaGetSymbolAddress((void**)&p_qkv, g_qkv);
        cudaGetSymbolAddress((void**)&p_o,   g_o);
        cudaGetSymbolAddress((void**)&p_h,   g_h);
        cudaGetSymbolAddress((void**)&p_f,   g_f);
    }

    const dim3 blk(256);
    const dim3 grid_qkv(D3 / BN,    T_TOKENS / BM);
    const dim3 grid_d  (DMODEL / BN, T_TOKENS / BM);
    const dim3 grid_ff (FFDIM / BN,  T_TOKENS / BM);

    for (int l = 0; l < 2; l++) {
        const float* hin  = (l == 0) ? x : p_h;
        float* hout2 = (l == 1) ? out : p_h;   // last FFN GEMM writes final output

        // pre-norm attention
        ln_kernel<<<T_TOKENS, blk>>>(hin, ln1_w + l * DMODEL, ln1_b + l * DMODEL, p_y);
        sgemm_tn<false, false><<<grid_qkv, blk>>>(
            p_y, Wqkv + (size_t)l * D3 * DMODEL, bqkv + (size_t)l * D3,
            nullptr, p_qkv, T_TOKENS, D3, DMODEL);
        attn_kernel<<<NWIN * NHEAD, blk>>>(p_qkv, p_o);
        sgemm_tn<false, true><<<grid_d, blk>>>(
            p_o, Wo + (size_t)l * DMODEL * DMODEL, bo + (size_t)l * DMODEL,
            hin, p_h, T_TOKENS, DMODEL, DMODEL);

        // pre-norm FFN
        ln_kernel<<<T_TOKENS, blk>>>(p_h, ln2_w + l * DMODEL, ln2_b + l * DMODEL, p_y);
        sgemm_tn<true, false><<<grid_ff, blk>>>(
            p_y, W1 + (size_t)l * FFDIM * DMODEL, b1 + (size_t)l * FFDIM,
            nullptr, p_f, T_TOKENS, FFDIM, DMODEL);
        sgemm_tn<false, true><<<grid_d, blk>>>(
            p_f, W2 + (size_t)l * DMODEL * FFDIM, b2 + (size_t)l * DMODEL,
            p_h, hout2, T_TOKENS, DMODEL, FFDIM);
    }
    (void)in_sizes; (void)n_in; (void)out_size;
}

// round 5
// speedup vs baseline: 1.5208x; 1.5208x over previous
#include <cuda_runtime.h>
#include <math.h>

// Problem constants
#define T_TOKENS 25088      // 8 * 3136
#define DMODEL   768
#define NHEAD    12
#define DHEAD    64
#define FFDIM    3072
#define WS2      49
#define NWIN     512        // T_TOKENS / 49
#define D3       2304       // 3 * DMODEL

// ---------------- scratch (device globals; no allocation allowed) ----------------
__device__ __align__(128) float g_y[(size_t)T_TOKENS * DMODEL];     // LN output
__device__ __align__(128) float g_qkv[(size_t)T_TOKENS * D3];       // QKV
__device__ __align__(128) float g_o[(size_t)T_TOKENS * DMODEL];     // attention output
__device__ __align__(128) float g_h[(size_t)T_TOKENS * DMODEL];     // residual stream
__device__ __align__(128) float g_f[(size_t)T_TOKENS * FFDIM];      // FFN hidden

// ---------------- LayerNorm: one block per token, 256 threads ----------------
__global__ __launch_bounds__(256) void ln_kernel(
    const float* __restrict__ x, const float* __restrict__ w,
    const float* __restrict__ b, float* __restrict__ y)
{
    const int t = blockIdx.x;
    const float* xr = x + (size_t)t * DMODEL;
    float* yr = y + (size_t)t * DMODEL;
    const int tid = threadIdx.x;

    float v0 = xr[tid];
    float v1 = xr[tid + 256];
    float v2 = xr[tid + 512];
    float s = v0 + v1 + v2;
    float q = v0 * v0 + v1 * v1 + v2 * v2;

    #pragma unroll
    for (int off = 16; off > 0; off >>= 1) {
        s += __shfl_xor_sync(0xFFFFFFFFu, s, off);
        q += __shfl_xor_sync(0xFFFFFFFFu, q, off);
    }
    __shared__ float ss[8], sq[8];
    const int wid = tid >> 5, lid = tid & 31;
    if (lid == 0) { ss[wid] = s; sq[wid] = q; }
    __syncthreads();
    if (tid == 0) {
        float S = 0.f, Q = 0.f;
        #pragma unroll
        for (int i = 0; i < 8; i++) { S += ss[i]; Q += sq[i]; }
        float m = S * (1.0f / DMODEL);
        float var = Q * (1.0f / DMODEL) - m * m;
        ss[0] = m;
        sq[0] = rsqrtf(var + 1e-5f);
    }
    __syncthreads();
    const float m = ss[0], r = sq[0];
    yr[tid]       = (v0 - m) * r * w[tid]       + b[tid];
    yr[tid + 256] = (v1 - m) * r * w[tid + 256] + b[tid + 256];
    yr[tid + 512] = (v2 - m) * r * w[tid + 512] + b[tid + 512];
}

// ---------------- Windowed attention: one block per (window, head) ----------------
__global__ __launch_bounds__(256) void attn_kernel(
    const float* __restrict__ qkv, float* __restrict__ o)
{
    __shared__ float sq[WS2 * DHEAD];
    __shared__ float sk[WS2 * DHEAD];
    __shared__ float sv[WS2 * DHEAD];
    __shared__ float sscr[WS2 * WS2];

    const int w  = blockIdx.x / NHEAD;
    const int hd = blockIdx.x % NHEAD;
    const int t0 = w * WS2;
    const int tid = threadIdx.x;

    for (int i = tid; i < WS2 * DHEAD; i += 256) {
        int r = i / DHEAD, d = i % DHEAD;
        size_t base = (size_t)(t0 + r) * D3 + hd * DHEAD + d;
        sq[i] = qkv[base];
        sk[i] = qkv[base + DMODEL];
        sv[i] = qkv[base + 2 * DMODEL];
    }
    __syncthreads();

    for (int i = tid; i < WS2 * WS2; i += 256) {
        int qi = i / WS2, kj = i % WS2;
        float acc = 0.f;
        #pragma unroll
        for (int d = 0; d < DHEAD; d++)
            acc = fmaf(sq[qi * DHEAD + d], sk[kj * DHEAD + d], acc);
        sscr[i] = acc * 0.125f;   // 1/sqrt(64)
    }
    __syncthreads();

    if (tid < WS2) {
        float mx = -1e30f;
        #pragma unroll 7
        for (int j = 0; j < WS2; j++) mx = fmaxf(mx, sscr[tid * WS2 + j]);
        float sum = 0.f;
        #pragma unroll 7
        for (int j = 0; j < WS2; j++) {
            float e = __expf(sscr[tid * WS2 + j] - mx);
            sscr[tid * WS2 + j] = e;
            sum += e;
        }
        float inv = 1.0f / sum;
        #pragma unroll 7
        for (int j = 0; j < WS2; j++) sscr[tid * WS2 + j] *= inv;
    }
    __syncthreads();

    for (int i = tid; i < WS2 * DHEAD; i += 256) {
        int qi = i / DHEAD, d = i % DHEAD;
        float acc = 0.f;
        #pragma unroll
        for (int kj = 0; kj < WS2; kj++)
            acc = fmaf(sscr[qi * WS2 + kj], sv[kj * DHEAD + d], acc);
        o[(size_t)(t0 + qi) * DMODEL + hd * DHEAD + d] = acc;
    }
}

// ---------------- bf16 helpers (no cuda_bf16.h; pure bit ops) ----------------
__device__ __forceinline__ unsigned f2bf(float f)
{
    unsigned u = __float_as_uint(f);
    return (u + 0x7FFFu + ((u >> 16) & 1u)) >> 16;   // round-to-nearest-even, low 16 bits
}

__device__ __forceinline__ float bf2f(unsigned h)
{
    return __uint_as_float(h << 16);
}

__device__ __forceinline__ unsigned smem_u32(const void* p)
{
    unsigned a;
    asm volatile("{ .reg .u64 t; cvta.to.shared.u64 t, %1; cvt.u32.u64 %0, t; }"
                 : "=r"(a) : "l"(p));
    return a;
}

__device__ __forceinline__ void ldsm4(unsigned* r, const unsigned* p)
{
    unsigned a = smem_u32(p);
    asm volatile("ldmatrix.sync.aligned.m8n8.x4.shared.b16 {%0,%1,%2,%3}, [%4];"
                 : "=r"(r[0]), "=r"(r[1]), "=r"(r[2]), "=r"(r[3]) : "r"(a));
}

__device__ __forceinline__ void mma16816(float* c, const unsigned* a, unsigned b0, unsigned b1)
{
    asm volatile("mma.sync.aligned.m16n8k16.row.col.f32.bf16.bf16.f32 "
                 "{%0,%1,%2,%3}, {%4,%5,%6,%7}, {%8,%9}, {%0,%1,%2,%3};"
                 : "+f"(c[0]), "+f"(c[1]), "+f"(c[2]), "+f"(c[3])
                 : "r"(a[0]), "r"(a[1]), "r"(a[2]), "r"(a[3]), "r"(b0), "r"(b1));
}

// ---------------- bf16x3 tensor-core GEMM ----------------
// C[M,N] = act(A[M,K] @ B[N,K]^T + bias) (+ res)
// A = Ah + Al, B = Bh + Bl (bf16 split); C = AhBh + AhBl + AlBh, fp32 accum.
// Block tile 128x128x32, 256 threads = 8 warps, warp tile 64x32, mma.m16n8k16.
// Shared planes store packed bf16 pairs (one unsigned = 2 elems), row stride 20 words.
#define GBM 128
#define GBN 128
#define GBK 32
#define LDP 20   // smem row stride in packed pairs (= 40 bf16 elems) -> conflict-free

template <bool GELU, bool RES>
__global__ __launch_bounds__(256) void gemm_tc(
    const float* __restrict__ A,     // [M,K]
    const float* __restrict__ B,     // [N,K]
    const float* __restrict__ bias,  // [N]
    const float* __restrict__ res,   // [M,N] or null
    float* __restrict__ C,           // [M,N]
    int M, int N, int K)
{
    __shared__ unsigned sAh[GBM * LDP];
    __shared__ unsigned sAl[GBM * LDP];
    __shared__ unsigned sBh[GBN * LDP];
    __shared__ unsigned sBl[GBN * LDP];

    const int bm = blockIdx.y * GBM;
    const int bn = blockIdx.x * GBN;
    const int tid = threadIdx.x;
    const int lane = tid & 31;
    const int wid = tid >> 5;
    const int wm = wid & 1;     // m offset 64*wm
    const int wn = wid >> 1;    // n offset 32*wn

    float acc[4][4][4];
    #pragma unroll
    for (int i = 0; i < 4; i++)
        #pragma unroll
        for (int j = 0; j < 4; j++)
            #pragma unroll
            for (int k = 0; k < 4; k++) acc[i][j][k] = 0.f;

    // gmem staging: each thread owns 4 float4 loads for A and for B per K-tile.
    const int lrow = tid >> 3;          // 0..31
    const int lcol = (tid & 7) * 4;     // 0,4,...,28 (float index in K-tile)
    const int spair = lrow * LDP + (tid & 7) * 2;   // packed-pair offset in smem row
    const float* Abase = A + (size_t)(bm + lrow) * K + lcol;
    const float* Bbase = B + (size_t)(bn + lrow) * K + lcol;
    const int nk = K / GBK;

    float4 pa0, pa1, pa2, pa3, pb0, pb1, pb2, pb3;

    // prologue load (kt = 0)
    pa0 = *(const float4*)(Abase);
    pa1 = *(const float4*)(Abase + (size_t)32 * K);
    pa2 = *(const float4*)(Abase + (size_t)64 * K);
    pa3 = *(const float4*)(Abase + (size_t)96 * K);
    pb0 = *(const float4*)(Bbase);
    pb1 = *(const float4*)(Bbase + (size_t)32 * K);
    pb2 = *(const float4*)(Bbase + (size_t)64 * K);
    pb3 = *(const float4*)(Bbase + (size_t)96 * K);

    for (int kt = 0; kt < nk; kt++) {
        // split prefetched registers into hi/lo planes in smem
        float vv[4];
        #pragma unroll
        for (int i = 0; i < 4; i++) {
            float4 va = (i == 0) ? pa0 : (i == 1) ? pa1 : (i == 2) ? pa2 : pa3;
            float4 vb = (i == 0) ? pb0 : (i == 1) ? pb1 : (i == 2) ? pb2 : pb3;
            const int so = i * 32 * LDP + spair;

            vv[0] = va.x; vv[1] = va.y; vv[2] = va.z; vv[3] = va.w;
            #pragma unroll
            for (int e = 0; e < 2; e++) {
                unsigned h0 = f2bf(vv[2 * e]);
                unsigned h1 = f2bf(vv[2 * e + 1]);
                unsigned l0 = f2bf(vv[2 * e] - bf2f(h0));
                unsigned l1 = f2bf(vv[2 * e + 1] - bf2f(h1));
                sAh[so + e] = h0 | (h1 << 16);
                sAl[so + e] = l0 | (l1 << 16);
            }
            vv[0] = vb.x; vv[1] = vb.y; vv[2] = vb.z; vv[3] = vb.w;
            #pragma unroll
            for (int e = 0; e < 2; e++) {
                unsigned h0 = f2bf(vv[2 * e]);
                unsigned h1 = f2bf(vv[2 * e + 1]);
                unsigned l0 = f2bf(vv[2 * e] - bf2f(h0));
                unsigned l1 = f2bf(vv[2 * e + 1] - bf2f(h1));
                sBh[so + e] = h0 | (h1 << 16);
                sBl[so + e] = l0 | (l1 << 16);
            }
        }
        __syncthreads();

        // prefetch next K-tile
        if (kt + 1 < nk) {
            const float* An = Abase + (size_t)(kt + 1) * GBK;
            const float* Bn = Bbase + (size_t)(kt + 1) * GBK;
            pa0 = *(const float4*)(An);
            pa1 = *(const float4*)(An + (size_t)32 * K);
            pa2 = *(const float4*)(An + (size_t)64 * K);
            pa3 = *(const float4*)(An + (size_t)96 * K);
            pb0 = *(const float4*)(Bn);
            pb1 = *(const float4*)(Bn + (size_t)32 * K);
            pb2 = *(const float4*)(Bn + (size_t)64 * K);
            pb3 = *(const float4*)(Bn + (size_t)96 * K);
        }

        #pragma unroll
        for (int ks = 0; ks < 2; ks++) {
            // per-lane ldmatrix source offsets (packed-pair units)
            const int aoff = (wm * 64 + (lane & 15)) * LDP + ks * 8 + ((lane >> 4) << 2);
            const int boff = (wn * 32 + (lane & 15)) * LDP + ks * 8 + ((lane >> 4) << 2);

            unsigned ah[4][4], al[4][4];
            #pragma unroll
            for (int mi = 0; mi < 4; mi++) {
                ldsm4(ah[mi], sAh + aoff + mi * 16 * LDP);
                ldsm4(al[mi], sAl + aoff + mi * 16 * LDP);
            }
            unsigned bh[2][4], bl[2][4];
            #pragma unroll
            for (int nj = 0; nj < 2; nj++) {
                ldsm4(bh[nj], sBh + boff + nj * 16 * LDP);
                ldsm4(bl[nj], sBl + boff + nj * 16 * LDP);
            }
            #pragma unroll
            for (int mi = 0; mi < 4; mi++) {
                #pragma unroll
                for (int ni = 0; ni < 4; ni++) {
                    const int nj = ni >> 1;
                    const int sel = ni & 1;
                    mma16816(acc[mi][ni], ah[mi], bh[nj][sel], bh[nj][sel + 2]); // Ah*Bh
                    mma16816(acc[mi][ni], ah[mi], bl[nj][sel], bl[nj][sel + 2]); // Ah*Bl
                    mma16816(acc[mi][ni], al[mi], bh[nj][sel], bh[nj][sel + 2]); // Al*Bh
                }
            }
        }
        __syncthreads();
    }

    // epilogue: c0,c1 -> (row, col..col+1); c2,c3 -> (row+8, ...)
    #pragma unroll
    for (int mi = 0; mi < 4; mi++) {
        #pragma unroll
        for (int ni = 0; ni < 4; ni++) {
            const int col = bn + wn * 32 + ni * 8 + (lane & 3) * 2;
            const float bs0 = bias[col];
            const float bs1 = bias[col + 1];
            #pragma unroll
            for (int half = 0; half < 2; half++) {
                const int row = bm + wm * 64 + mi * 16 + (lane >> 2) + half * 8;
                float v0 = acc[mi][ni][half * 2 + 0] + bs0;
                float v1 = acc[mi][ni][half * 2 + 1] + bs1;
                if (GELU) {
                    v0 = 0.5f * v0 * (1.0f + erff(v0 * 0.70710678118654752f));
                    v1 = 0.5f * v1 * (1.0f + erff(v1 * 0.70710678118654752f));
                }
                if (RES) {
                    float2 r2 = *(const float2*)(res + (size_t)row * N + col);
                    v0 += r2.x;
                    v1 += r2.y;
                }
                float2 o2;
                o2.x = v0;
                o2.y = v1;
                *(float2*)(C + (size_t)row * N + col) = o2;
            }
        }
    }
    (void)M;
}

// ---------------- host-side launch ----------------
extern "C" void kernel_launch(void* const* d_in, const int* in_sizes, int n_in,
                              void* d_out, int out_size)
{
    const float* x     = (const float*)d_in[0];
    const float* Wqkv  = (const float*)d_in[1];
    const float* bqkv  = (const float*)d_in[2];
    const float* Wo    = (const float*)d_in[3];
    const float* bo    = (const float*)d_in[4];
    const float* ln1_w = (const float*)d_in[5];
    const float* ln1_b = (const float*)d_in[6];
    const float* W1    = (const float*)d_in[7];
    const float* b1    = (const float*)d_in[8];
    const float* W2    = (const float*)d_in[9];
    const float* b2    = (const float*)d_in[10];
    const float* ln2_w = (const float*)d_in[11];
    const float* ln2_b = (const float*)d_in[12];
    float* out = (float*)d_out;

    static float *p_y = nullptr, *p_qkv = nullptr, *p_o = nullptr, *p_h = nullptr, *p_f = nullptr;
    if (!p_y) {
        cudaGetSymbolAddress((void**)&p_y,   g_y);
        cudaGetSymbolAddress((void**)&p_qkv, g_qkv);
        cudaGetSymbolAddress((void**)&p_o,   g_o);
        cudaGetSymbolAddress((void**)&p_h,   g_h);
        cudaGetSymbolAddress((void**)&p_f,   g_f);
    }

    const dim3 blk(256);
    const dim3 grid_qkv(D3 / GBN,    T_TOKENS / GBM);
    const dim3 grid_d  (DMODEL / GBN, T_TOKENS / GBM);
    const dim3 grid_ff (FFDIM / GBN,  T_TOKENS / GBM);

    for (int l = 0; l < 2; l++) {
        const float* hin  = (l == 0) ? x : p_h;
        float* hout2 = (l == 1) ? out : p_h;   // last FFN GEMM writes final output

        // pre-norm attention
        ln_kernel<<<T_TOKENS, blk>>>(hin, ln1_w + l * DMODEL, ln1_b + l * DMODEL, p_y);
        gemm_tc<false, false><<<grid_qkv, blk>>>(
            p_y, Wqkv + (size_t)l * D3 * DMODEL, bqkv + (size_t)l * D3,
            nullptr, p_qkv, T_TOKENS, D3, DMODEL);
        attn_kernel<<<NWIN * NHEAD, blk>>>(p_qkv, p_o);
        gemm_tc<false, true><<<grid_d, blk>>>(
            p_o, Wo + (size_t)l * DMODEL * DMODEL, bo + (size_t)l * DMODEL,
            hin, p_h, T_TOKENS, DMODEL, DMODEL);

        // pre-norm FFN
        ln_kernel<<<T_TOKENS, blk>>>(p_h, ln2_w + l * DMODEL, ln2_b + l * DMODEL, p_y);
        gemm_tc<true, false><<<grid_ff, blk>>>(
            p_y, W1 + (size_t)l * FFDIM * DMODEL, b1 + (size_t)l * FFDIM,
            nullptr, p_f, T_TOKENS, FFDIM, DMODEL);
        gemm_tc<false, true><<<grid_d, blk>>>(
            p_f, W2 + (size_t)l * DMODEL * FFDIM, b2 + (size_t)l * DMODEL,
            p_h, hout2, T_TOKENS, DMODEL, FFDIM);
    }
    (void)in_sizes; (void)n_in; (void)out_size;
}

// round 6
// speedup vs baseline: 1.6157x; 1.0624x over previous
#include <cuda_runtime.h>
#include <math.h>

// Problem constants
#define T_TOKENS 25088      // 8 * 3136
#define DMODEL   768
#define NHEAD    12
#define DHEAD    64
#define FFDIM    3072
#define WS2      49
#define NWIN     512        // T_TOKENS / 49
#define D3       2304       // 3 * DMODEL

// ---------------- scratch (device globals; no allocation allowed) ----------------
__device__ __align__(128) float g_qkv[(size_t)T_TOKENS * D3];       // QKV (fp32)
__device__ __align__(128) float g_h[(size_t)T_TOKENS * DMODEL];     // residual stream
// bf16 hi/lo planes
__device__ __align__(128) unsigned short g_yh[(size_t)T_TOKENS * DMODEL];
__device__ __align__(128) unsigned short g_yl[(size_t)T_TOKENS * DMODEL];
__device__ __align__(128) unsigned short g_oh[(size_t)T_TOKENS * DMODEL];
__device__ __align__(128) unsigned short g_ol[(size_t)T_TOKENS * DMODEL];
__device__ __align__(128) unsigned short g_fh[(size_t)T_TOKENS * FFDIM];
__device__ __align__(128) unsigned short g_fl[(size_t)T_TOKENS * FFDIM];
__device__ __align__(128) unsigned short g_wh[(size_t)FFDIM * DMODEL];
__device__ __align__(128) unsigned short g_wl[(size_t)FFDIM * DMODEL];

// ---------------- bf16 helpers (pure bit ops) ----------------
__device__ __forceinline__ unsigned f2bf(float f)
{
    unsigned u = __float_as_uint(f);
    return (u + 0x7FFFu + ((u >> 16) & 1u)) >> 16;
}

__device__ __forceinline__ float bf2f(unsigned h)
{
    return __uint_as_float(h << 16);
}

// ---------------- weight split: fp32 -> hi/lo bf16 planes ----------------
__global__ __launch_bounds__(256) void split_kernel(
    const float* __restrict__ src, unsigned short* __restrict__ hi,
    unsigned short* __restrict__ lo)
{
    const int i = (blockIdx.x * 256 + threadIdx.x) * 4;
    float4 v = *(const float4*)(src + i);
    unsigned h0 = f2bf(v.x);
    unsigned h1 = f2bf(v.y);
    unsigned h2 = f2bf(v.z);
    unsigned h3 = f2bf(v.w);
    unsigned l0 = f2bf(v.x - bf2f(h0));
    unsigned l1 = f2bf(v.y - bf2f(h1));
    unsigned l2 = f2bf(v.z - bf2f(h2));
    unsigned l3 = f2bf(v.w - bf2f(h3));
    uint2 ph;
    ph.x = h0 | (h1 << 16);
    ph.y = h2 | (h3 << 16);
    *(uint2*)(hi + i) = ph;
    uint2 pl;
    pl.x = l0 | (l1 << 16);
    pl.y = l2 | (l3 << 16);
    *(uint2*)(lo + i) = pl;
}

// ---------------- LayerNorm: one block per token; writes hi/lo planes -------------
__global__ __launch_bounds__(256) void ln_kernel(
    const float* __restrict__ x, const float* __restrict__ w,
    const float* __restrict__ b, unsigned short* __restrict__ yh,
    unsigned short* __restrict__ yl)
{
    const int t = blockIdx.x;
    const float* xr = x + (size_t)t * DMODEL;
    unsigned short* yhr = yh + (size_t)t * DMODEL;
    unsigned short* ylr = yl + (size_t)t * DMODEL;
    const int tid = threadIdx.x;

    float v0 = xr[tid];
    float v1 = xr[tid + 256];
    float v2 = xr[tid + 512];
    float s = v0 + v1 + v2;
    float q = v0 * v0 + v1 * v1 + v2 * v2;

    #pragma unroll
    for (int off = 16; off > 0; off >>= 1) {
        s += __shfl_xor_sync(0xFFFFFFFFu, s, off);
        q += __shfl_xor_sync(0xFFFFFFFFu, q, off);
    }
    __shared__ float ss[8], sq[8];
    const int wid = tid >> 5, lid = tid & 31;
    if (lid == 0) { ss[wid] = s; sq[wid] = q; }
    __syncthreads();
    if (tid == 0) {
        float S = 0.f, Q = 0.f;
        #pragma unroll
        for (int i = 0; i < 8; i++) { S += ss[i]; Q += sq[i]; }
        float m = S * (1.0f / DMODEL);
        float var = Q * (1.0f / DMODEL) - m * m;
        ss[0] = m;
        sq[0] = rsqrtf(var + 1e-5f);
    }
    __syncthreads();
    const float m = ss[0], r = sq[0];
    float o0 = (v0 - m) * r * w[tid]       + b[tid];
    float o1 = (v1 - m) * r * w[tid + 256] + b[tid + 256];
    float o2 = (v2 - m) * r * w[tid + 512] + b[tid + 512];
    unsigned h0 = f2bf(o0);
    unsigned h1 = f2bf(o1);
    unsigned h2 = f2bf(o2);
    yhr[tid]       = (unsigned short)h0;
    yhr[tid + 256] = (unsigned short)h1;
    yhr[tid + 512] = (unsigned short)h2;
    ylr[tid]       = (unsigned short)f2bf(o0 - bf2f(h0));
    ylr[tid + 256] = (unsigned short)f2bf(o1 - bf2f(h1));
    ylr[tid + 512] = (unsigned short)f2bf(o2 - bf2f(h2));
}

// ---------------- Windowed attention: g_qkv -> o hi/lo planes ----------------
__global__ __launch_bounds__(256) void attn_kernel(
    const float* __restrict__ qkv, unsigned short* __restrict__ oh,
    unsigned short* __restrict__ ol)
{
    __shared__ float sq[WS2 * DHEAD];
    __shared__ float sk[WS2 * DHEAD];
    __shared__ float sv[WS2 * DHEAD];
    __shared__ float sscr[WS2 * WS2];

    const int w  = blockIdx.x / NHEAD;
    const int hd = blockIdx.x % NHEAD;
    const int t0 = w * WS2;
    const int tid = threadIdx.x;

    for (int i = tid; i < WS2 * DHEAD; i += 256) {
        int r = i / DHEAD, d = i % DHEAD;
        size_t base = (size_t)(t0 + r) * D3 + hd * DHEAD + d;
        sq[i] = qkv[base];
        sk[i] = qkv[base + DMODEL];
        sv[i] = qkv[base + 2 * DMODEL];
    }
    __syncthreads();

    for (int i = tid; i < WS2 * WS2; i += 256) {
        int qi = i / WS2, kj = i % WS2;
        float acc = 0.f;
        #pragma unroll
        for (int d = 0; d < DHEAD; d++)
            acc = fmaf(sq[qi * DHEAD + d], sk[kj * DHEAD + d], acc);
        sscr[i] = acc * 0.125f;
    }
    __syncthreads();

    if (tid < WS2) {
        float mx = -1e30f;
        #pragma unroll 7
        for (int j = 0; j < WS2; j++) mx = fmaxf(mx, sscr[tid * WS2 + j]);
        float sum = 0.f;
        #pragma unroll 7
        for (int j = 0; j < WS2; j++) {
            float e = __expf(sscr[tid * WS2 + j] - mx);
            sscr[tid * WS2 + j] = e;
            sum += e;
        }
        float inv = 1.0f / sum;
        #pragma unroll 7
        for (int j = 0; j < WS2; j++) sscr[tid * WS2 + j] *= inv;
    }
    __syncthreads();

    for (int i = tid; i < WS2 * DHEAD; i += 256) {
        int qi = i / DHEAD, d = i % DHEAD;
        float acc = 0.f;
        #pragma unroll
        for (int kj = 0; kj < WS2; kj++)
            acc = fmaf(sscr[qi * WS2 + kj], sv[kj * DHEAD + d], acc);
        size_t oidx = (size_t)(t0 + qi) * DMODEL + hd * DHEAD + d;
        unsigned h = f2bf(acc);
        oh[oidx] = (unsigned short)h;
        ol[oidx] = (unsigned short)f2bf(acc - bf2f(h));
    }
}

// ---------------- mma helpers ----------------
__device__ __forceinline__ unsigned smem_u32(const void* p)
{
    unsigned a;
    asm volatile("{ .reg .u64 t; cvta.to.shared.u64 t, %1; cvt.u32.u64 %0, t; }"
                 : "=r"(a) : "l"(p));
    return a;
}

__device__ __forceinline__ void ldsm4(unsigned* r, const unsigned* p)
{
    unsigned a = smem_u32(p);
    asm volatile("ldmatrix.sync.aligned.m8n8.x4.shared.b16 {%0,%1,%2,%3}, [%4];"
                 : "=r"(r[0]), "=r"(r[1]), "=r"(r[2]), "=r"(r[3]) : "r"(a));
}

__device__ __forceinline__ void mma16816(float* c, const unsigned* a, unsigned b0, unsigned b1)
{
    asm volatile("mma.sync.aligned.m16n8k16.row.col.f32.bf16.bf16.f32 "
                 "{%0,%1,%2,%3}, {%4,%5,%6,%7}, {%8,%9}, {%0,%1,%2,%3};"
                 : "+f"(c[0]), "+f"(c[1]), "+f"(c[2]), "+f"(c[3])
                 : "r"(a[0]), "r"(a[1]), "r"(a[2]), "r"(a[3]), "r"(b0), "r"(b1));
}

// ---------------- bf16x3 tensor-core GEMM (preconverted hi/lo planes) -------------
// C = act(A @ B^T + bias) (+ res);  A planes [M,K], B planes [N,K].
// Block tile 128x128x32, 8 warps, warp tile 64x32, mma.m16n8k16.
#define GBM 128
#define GBN 128
#define GBK 32
#define LDP 20   // smem row stride in 32-bit words (= 40 bf16) -> conflict-free

template <bool GELU, bool RES, bool SPLITOUT>
__global__ __launch_bounds__(256) void gemm_tc(
    const unsigned short* __restrict__ Ah, const unsigned short* __restrict__ Al,
    const unsigned short* __restrict__ Bh, const unsigned short* __restrict__ Bl,
    const float* __restrict__ bias,
    const float* __restrict__ res,
    float* __restrict__ C,
    unsigned short* __restrict__ Ch, unsigned short* __restrict__ Cl,
    int N, int K)
{
    __shared__ unsigned sAh[GBM * LDP];
    __shared__ unsigned sAl[GBM * LDP];
    __shared__ unsigned sBh[GBN * LDP];
    __shared__ unsigned sBl[GBN * LDP];

    const int bm = blockIdx.y * GBM;
    const int bn = blockIdx.x * GBN;
    const int tid = threadIdx.x;
    const int lane = tid & 31;
    const int wid = tid >> 5;
    const int wm = wid & 1;     // m offset 64*wm
    const int wn = wid >> 1;    // n offset 32*wn

    float acc[4][4][4];
    #pragma unroll
    for (int i = 0; i < 4; i++)
        #pragma unroll
        for (int j = 0; j < 4; j++)
            #pragma unroll
            for (int k = 0; k < 4; k++) acc[i][j][k] = 0.f;

    // loader: thread handles rows lrow4 and lrow4+64, 16B chunk qch (8 bf16)
    const int lrow4 = tid >> 2;          // 0..63
    const int qch   = tid & 3;           // 0..3
    const unsigned short* pAh = Ah + (size_t)(bm + lrow4) * K + qch * 8;
    const unsigned short* pAl = Al + (size_t)(bm + lrow4) * K + qch * 8;
    const unsigned short* pBh = Bh + (size_t)(bn + lrow4) * K + qch * 8;
    const unsigned short* pBl = Bl + (size_t)(bn + lrow4) * K + qch * 8;
    const size_t rstep = (size_t)64 * K;
    const int sb0 = lrow4 * LDP + qch * 4;
    const int sb1 = (lrow4 + 64) * LDP + qch * 4;
    const int nk = K / GBK;

    uint4 rah0, rah1, ral0, ral1, rbh0, rbh1, rbl0, rbl1;

    rah0 = *(const uint4*)(pAh);
    rah1 = *(const uint4*)(pAh + rstep);
    ral0 = *(const uint4*)(pAl);
    ral1 = *(const uint4*)(pAl + rstep);
    rbh0 = *(const uint4*)(pBh);
    rbh1 = *(const uint4*)(pBh + rstep);
    rbl0 = *(const uint4*)(pBl);
    rbl1 = *(const uint4*)(pBl + rstep);

    for (int kt = 0; kt < nk; kt++) {
        *(uint4*)(sAh + sb0) = rah0;
        *(uint4*)(sAh + sb1) = rah1;
        *(uint4*)(sAl + sb0) = ral0;
        *(uint4*)(sAl + sb1) = ral1;
        *(uint4*)(sBh + sb0) = rbh0;
        *(uint4*)(sBh + sb1) = rbh1;
        *(uint4*)(sBl + sb0) = rbl0;
        *(uint4*)(sBl + sb1) = rbl1;
        __syncthreads();

        if (kt + 1 < nk) {
            const int ko = (kt + 1) * GBK;
            rah0 = *(const uint4*)(pAh + ko);
            rah1 = *(const uint4*)(pAh + ko + rstep);
            ral0 = *(const uint4*)(pAl + ko);
            ral1 = *(const uint4*)(pAl + ko + rstep);
            rbh0 = *(const uint4*)(pBh + ko);
            rbh1 = *(const uint4*)(pBh + ko + rstep);
            rbl0 = *(const uint4*)(pBl + ko);
            rbl1 = *(const uint4*)(pBl + ko + rstep);
        }

        #pragma unroll
        for (int ks = 0; ks < 2; ks++) {
            const int aoff = (wm * 64 + (lane & 15)) * LDP + ks * 8 + ((lane >> 4) << 2);
            const int boff = (wn * 32 + (lane & 15)) * LDP + ks * 8 + ((lane >> 4) << 2);

            unsigned ah[4][4], al[4][4];
            #pragma unroll
            for (int mi = 0; mi < 4; mi++) {
                ldsm4(ah[mi], sAh + aoff + mi * 16 * LDP);
                ldsm4(al[mi], sAl + aoff + mi * 16 * LDP);
            }
            unsigned bh[2][4], bl[2][4];
            #pragma unroll
            for (int nj = 0; nj < 2; nj++) {
                ldsm4(bh[nj], sBh + boff + nj * 16 * LDP);
                ldsm4(bl[nj], sBl + boff + nj * 16 * LDP);
            }
            #pragma unroll
            for (int mi = 0; mi < 4; mi++) {
                #pragma unroll
                for (int ni = 0; ni < 4; ni++) {
                    const int nj = ni >> 1;
                    const int sel = ni & 1;
                    mma16816(acc[mi][ni], ah[mi], bh[nj][sel], bh[nj][sel + 2]); // Ah*Bh
                    mma16816(acc[mi][ni], ah[mi], bl[nj][sel], bl[nj][sel + 2]); // Ah*Bl
                    mma16816(acc[mi][ni], al[mi], bh[nj][sel], bh[nj][sel + 2]); // Al*Bh
                }
            }
        }
        __syncthreads();
    }

    // epilogue
    #pragma unroll
    for (int mi = 0; mi < 4; mi++) {
        #pragma unroll
        for (int ni = 0; ni < 4; ni++) {
            const int col = bn + wn * 32 + ni * 8 + (lane & 3) * 2;
            const float bs0 = bias[col];
            const float bs1 = bias[col + 1];
            #pragma unroll
            for (int half = 0; half < 2; half++) {
                const int row = bm + wm * 64 + mi * 16 + (lane >> 2) + half * 8;
                float v0 = acc[mi][ni][half * 2 + 0] + bs0;
                float v1 = acc[mi][ni][half * 2 + 1] + bs1;
                if (GELU) {
                    v0 = 0.5f * v0 * (1.0f + erff(v0 * 0.70710678118654752f));
                    v1 = 0.5f * v1 * (1.0f + erff(v1 * 0.70710678118654752f));
                }
                if (RES) {
                    float2 r2 = *(const float2*)(res + (size_t)row * N + col);
                    v0 += r2.x;
                    v1 += r2.y;
                }
                if (SPLITOUT) {
                    unsigned h0 = f2bf(v0);
                    unsigned h1 = f2bf(v1);
                    unsigned l0 = f2bf(v0 - bf2f(h0));
                    unsigned l1 = f2bf(v1 - bf2f(h1));
                    *(unsigned*)(Ch + (size_t)row * N + col) = h0 | (h1 << 16);
                    *(unsigned*)(Cl + (size_t)row * N + col) = l0 | (l1 << 16);
                } else {
                    float2 o2;
                    o2.x = v0;
                    o2.y = v1;
                    *(float2*)(C + (size_t)row * N + col) = o2;
                }
            }
        }
    }
}

// ---------------- host-side launch ----------------
extern "C" void kernel_launch(void* const* d_in, const int* in_sizes, int n_in,
                              void* d_out, int out_size)
{
    const float* x     = (const float*)d_in[0];
    const float* Wqkv  = (const float*)d_in[1];
    const float* bqkv  = (const float*)d_in[2];
    const float* Wo    = (const float*)d_in[3];
    const float* bo    = (const float*)d_in[4];
    const float* ln1_w = (const float*)d_in[5];
    const float* ln1_b = (const float*)d_in[6];
    const float* W1    = (const float*)d_in[7];
    const float* b1    = (const float*)d_in[8];
    const float* W2    = (const float*)d_in[9];
    const float* b2    = (const float*)d_in[10];
    const float* ln2_w = (const float*)d_in[11];
    const float* ln2_b = (const float*)d_in[12];
    float* out = (float*)d_out;

    static float *p_qkv = nullptr, *p_h = nullptr;
    static unsigned short *p_yh = nullptr, *p_yl = nullptr, *p_oh = nullptr, *p_ol = nullptr;
    static unsigned short *p_fh = nullptr, *p_fl = nullptr, *p_wh = nullptr, *p_wl = nullptr;
    if (!p_qkv) {
        cudaGetSymbolAddress((void**)&p_qkv, g_qkv);
        cudaGetSymbolAddress((void**)&p_h,   g_h);
        cudaGetSymbolAddress((void**)&p_yh,  g_yh);
        cudaGetSymbolAddress((void**)&p_yl,  g_yl);
        cudaGetSymbolAddress((void**)&p_oh,  g_oh);
        cudaGetSymbolAddress((void**)&p_ol,  g_ol);
        cudaGetSymbolAddress((void**)&p_fh,  g_fh);
        cudaGetSymbolAddress((void**)&p_fl,  g_fl);
        cudaGetSymbolAddress((void**)&p_wh,  g_wh);
        cudaGetSymbolAddress((void**)&p_wl,  g_wl);
    }

    const dim3 blk(256);
    const dim3 grid_qkv(D3 / GBN,     T_TOKENS / GBM);
    const dim3 grid_d  (DMODEL / GBN, T_TOKENS / GBM);
    const dim3 grid_ff (FFDIM / GBN,  T_TOKENS / GBM);

    for (int l = 0; l < 2; l++) {
        const float* hin  = (l == 0) ? x : p_h;
        float* hout2 = (l == 1) ? out : p_h;   // last FFN GEMM writes final output

        // pre-norm attention
        ln_kernel<<<T_TOKENS, blk>>>(hin, ln1_w + l * DMODEL, ln1_b + l * DMODEL, p_yh, p_yl);
        split_kernel<<<(D3 * DMODEL) / 1024, blk>>>(Wqkv + (size_t)l * D3 * DMODEL, p_wh, p_wl);
        gemm_tc<false, false, false><<<grid_qkv, blk>>>(
            p_yh, p_yl, p_wh, p_wl, bqkv + (size_t)l * D3,
            nullptr, p_qkv, nullptr, nullptr, D3, DMODEL);
        attn_kernel<<<NWIN * NHEAD, blk>>>(p_qkv, p_oh, p_ol);
        split_kernel<<<(DMODEL * DMODEL) / 1024, blk>>>(Wo + (size_t)l * DMODEL * DMODEL, p_wh, p_wl);
        gemm_tc<false, true, false><<<grid_d, blk>>>(
            p_oh, p_ol, p_wh, p_wl, bo + (size_t)l * DMODEL,
            hin, p_h, nullptr, nullptr, DMODEL, DMODEL);

        // pre-norm FFN
        ln_kernel<<<T_TOKENS, blk>>>(p_h, ln2_w + l * DMODEL, ln2_b + l * DMODEL, p_yh, p_yl);
        split_kernel<<<(FFDIM * DMODEL) / 1024, blk>>>(W1 + (size_t)l * FFDIM * DMODEL, p_wh, p_wl);
        gemm_tc<true, false, true><<<grid_ff, blk>>>(
            p_yh, p_yl, p_wh, p_wl, b1 + (size_t)l * FFDIM,
            nullptr, nullptr, p_fh, p_fl, FFDIM, DMODEL);
        split_kernel<<<(DMODEL * FFDIM) / 1024, blk>>>(W2 + (size_t)l * DMODEL * FFDIM, p_wh, p_wl);
        gemm_tc<false, true, false><<<grid_d, blk>>>(
            p_fh, p_fl, p_wh, p_wl, b2 + (size_t)l * DMODEL,
            p_h, hout2, nullptr, nullptr, DMODEL, FFDIM);
    }
    (void)in_sizes; (void)n_in; (void)out_size;
}